// round 14
// baseline (speedup 1.0000x reference)
#include <cuda_runtime.h>
#include <cuda_fp16.h>
#include <cstdint>

// ---------------- problem constants ----------------
#define VOCAB 32000
#define EMB   64
#define BATCH 4
#define SEQ   2048
#define MROWS (BATCH * SEQ)   // 8192

// GEMM tiling
#define BM 128
#define BN 128

// device scratch
__device__ __half g_Af[MROWS * EMB];        // prefix means, fp16, mma-fragment order
__device__ float  g_csum[BATCH * 32 * EMB]; // per-chunk sums
__device__ int    g_c1 = 0;                 // grid-barrier arrive counter
__device__ int    g_c2 = 0;                 // exit counter (for reset)

// ---------------- helpers ----------------
__device__ __forceinline__ uint32_t h2_bits(__half2 h) {
    return *reinterpret_cast<uint32_t*>(&h);
}
__device__ __forceinline__ void mma_f16(float c[4],
                                        uint32_t a0, uint32_t a1, uint32_t a2, uint32_t a3,
                                        uint32_t b0, uint32_t b1) {
    asm volatile(
        "mma.sync.aligned.m16n8k16.row.col.f32.f16.f16.f32 "
        "{%0,%1,%2,%3}, {%4,%5,%6,%7}, {%8,%9}, {%0,%1,%2,%3};"
        : "+f"(c[0]), "+f"(c[1]), "+f"(c[2]), "+f"(c[3])
        : "r"(a0), "r"(a1), "r"(a2), "r"(a3), "r"(b0), "r"(b1));
}

// column permutation within each 16-row group of the B tile (epilogue contiguity)
__device__ __forceinline__ int bperm(int q) {
    const int q7 = q & 7;
    return ((q7 >> 1) << 2) + (q & 1) + ((q & 8) ? 2 : 0);
}

// ---------------- fused prep: gather + scan + grid-barrier + offset + fragment store ------
// grid (32, BATCH) = 128 blocks, all co-resident (<=148 SMs) -> spin barrier is safe.
__global__ void __launch_bounds__(512) prep_kernel(const float* __restrict__ emb,
                                                   const int* __restrict__ x) {
    __shared__ float ebuf[64 * 64];   // chunk embeddings -> in-place inclusive scan
    __shared__ float part[8 * 64];    // parallel offset partials
    __shared__ float off[64];

    const int c = blockIdx.x, b = blockIdx.y;
    const int t = threadIdx.x;
    const int i = t >> 3, q = t & 7;  // position in chunk / feature octet
    const int p0 = c * 64;

    // ---- phase 1: gather + chunk-local scan, publish chunk sum ----
    {
        const int idx = x[b * SEQ + p0 + i];
        const float4* src = reinterpret_cast<const float4*>(emb + (size_t)idx * EMB) + q * 2;
        float4 v0 = src[0];
        float4 v1 = src[1];
        *reinterpret_cast<float4*>(ebuf + i * 64 + q * 8)     = v0;
        *reinterpret_cast<float4*>(ebuf + i * 64 + q * 8 + 4) = v1;
    }
    __syncthreads();
    if (t < 64) {
        float run = 0.0f;
        #pragma unroll 8
        for (int p = 0; p < 64; ++p) {
            run += ebuf[p * 64 + t];
            ebuf[p * 64 + t] = run;
        }
        g_csum[(b * 32 + c) * EMB + t] = run;
    }
    __syncthreads();

    // ---- grid barrier: arrive + spin (lane 0), then block-barrier ----
    if (t == 0) {
        __threadfence();                       // csum visible before arrive
        atomicAdd(&g_c1, 1);
        while (atomicAdd(&g_c1, 0) < 128) __nanosleep(64);
        __threadfence();                       // others' csums visible after
    }
    __syncthreads();

    // ---- phase 2: offset = sum of predecessor chunk sums (parallel 8-way) ----
    {
        const int g = t >> 6;    // 0..7
        const int e = t & 63;
        float partial = 0.0f;
        for (int cc = g; cc < c; cc += 8)
            partial += g_csum[(b * 32 + cc) * EMB + e];
        part[g * 64 + e] = partial;
    }
    __syncthreads();
    if (t < 64) {
        float o = 0.0f;
        #pragma unroll
        for (int gg = 0; gg < 8; ++gg) o += part[gg * 64 + t];
        off[t] = o;
    }
    __syncthreads();

    // ---- apply offset, scale, fp16-round, FRAGMENT-ORDER store to g_Af ----
    {
        const int p = p0 + i;
        const float inv = __fdividef(1.0f, (float)(p + 1));
        const float* sb = ebuf + i * 64 + q * 8;
        const float* ob = off + q * 8;
        uint32_t h[4];
        h[0] = h2_bits(__floats2half2_rn((sb[0] + ob[0]) * inv, (sb[1] + ob[1]) * inv));
        h[1] = h2_bits(__floats2half2_rn((sb[2] + ob[2]) * inv, (sb[3] + ob[3]) * inv));
        h[2] = h2_bits(__floats2half2_rn((sb[4] + ob[4]) * inv, (sb[5] + ob[5]) * inv));
        h[3] = h2_bits(__floats2half2_rn((sb[6] + ob[6]) * inv, (sb[7] + ob[7]) * inv));

        const int m    = b * SEQ + p;
        const int Tm   = m >> 4;
        const int r    = m & 15;
        const int gid8 = r & 7;
        const int hi   = r >> 3;
        const int ks   = q >> 1;
        const int hh   = q & 1;
        const int slot = hh * 2 + hi;

        uint32_t* dst = reinterpret_cast<uint32_t*>(g_Af) +
                        ((size_t)(Tm * 4 + ks) * 32 + gid8 * 4) * 4 + slot;
        #pragma unroll
        for (int d = 0; d < 4; ++d) dst[d * 4] = h[d];
    }

    // ---- reset barrier counters for the next graph replay (last block out) ----
    __syncthreads();
    if (t == 0) {
        const int v = atomicAdd(&g_c2, 1);
        if (v == 127) {
            g_c1 = 0;
            g_c2 = 0;
            __threadfence();
        }
    }
}

// ---------------- GEMM: fp16 mma.sync, register B, bias-seeded accumulators --------------
// out[m, n] = sum_k A[m,k] * W[n,k] + bias[n]   (byte-identical to round 13)
__global__ void __launch_bounds__(256, 2) gemm_kernel(const float* __restrict__ Wm,
                                                      const float* __restrict__ bias,
                                                      float* __restrict__ out) {
    const int tid  = threadIdx.x;
    const int wid  = tid >> 5;
    const int lane = tid & 31;
    const int gid  = lane >> 2;   // 0..7
    const int tig  = lane & 3;    // 0..3
    const int mw   = wid >> 2;    // warp M index 0..1
    const int nw   = wid & 3;     // warp N index 0..3
    const int n0   = blockIdx.x * BN;
    const int yb   = blockIdx.y;  // 0..7

    // ---- B fragments -> registers (constant across the whole j-loop) ----
    uint32_t bb[4][4][2];   // [nt][ks][half]
    #pragma unroll
    for (int nt = 0; nt < 4; ++nt) {
        const int r  = nw * 32 + nt * 8 + gid;
        const int wr = (r & ~15) + bperm(r & 15);
        const float* wrow = Wm + (size_t)(n0 + wr) * EMB;
        #pragma unroll
        for (int ks = 0; ks < 4; ++ks) {
            float2 lo = *reinterpret_cast<const float2*>(wrow + ks * 16 + 2 * tig);
            float2 hi = *reinterpret_cast<const float2*>(wrow + ks * 16 + 8 + 2 * tig);
            bb[nt][ks][0] = h2_bits(__floats2half2_rn(lo.x, lo.y));
            bb[nt][ks][1] = h2_bits(__floats2half2_rn(hi.x, hi.y));
        }
    }

    // bias -> persistent registers (post-perm contiguous cols)
    float4 bias_r[2];
    #pragma unroll
    for (int p = 0; p < 2; ++p)
        bias_r[p] = *reinterpret_cast<const float4*>(bias + n0 + nw * 32 + p * 16 + 4 * tig);

    const uint4* __restrict__ Af = reinterpret_cast<const uint4*>(g_Af);

    #pragma unroll 1
    for (int j = 0; j < 8; ++j) {
        const int Tbase = ((yb + j * 8) * 8 + mw * 4);

        // accumulators seeded with bias
        float acc[4][4][4];
        #pragma unroll
        for (int mt = 0; mt < 4; ++mt) {
            #pragma unroll
            for (int p = 0; p < 2; ++p) {
                const float4 bv = bias_r[p];
                acc[mt][2 * p][0] = bv.x;  acc[mt][2 * p][1] = bv.y;
                acc[mt][2 * p][2] = bv.x;  acc[mt][2 * p][3] = bv.y;
                acc[mt][2 * p + 1][0] = bv.z;  acc[mt][2 * p + 1][1] = bv.w;
                acc[mt][2 * p + 1][2] = bv.z;  acc[mt][2 * p + 1][3] = bv.w;
            }
        }

        #pragma unroll
        for (int ks = 0; ks < 4; ++ks) {
            uint4 av[4];
            #pragma unroll
            for (int mt = 0; mt < 4; ++mt)
                av[mt] = Af[(size_t)((Tbase + mt) * 4 + ks) * 32 + lane];
            #pragma unroll
            for (int mt = 0; mt < 4; ++mt)
                #pragma unroll
                for (int nt = 0; nt < 4; ++nt)
                    mma_f16(acc[mt][nt], av[mt].x, av[mt].y, av[mt].z, av[mt].w,
                            bb[nt][ks][0], bb[nt][ks][1]);
        }

        // ---- epilogue: pure packing + streaming STG ----
        const int m0 = (yb + j * 8) * BM;
        #pragma unroll
        for (int mt = 0; mt < 4; ++mt) {
            const int row0 = m0 + mw * 64 + mt * 16 + gid;
            float* orow = out + (size_t)row0 * VOCAB + n0 + nw * 32 + 4 * tig;
            #pragma unroll
            for (int p = 0; p < 2; ++p) {
                float4 v0, v1;
                v0.x = acc[mt][2 * p][0];
                v0.y = acc[mt][2 * p][1];
                v0.z = acc[mt][2 * p + 1][0];
                v0.w = acc[mt][2 * p + 1][1];
                v1.x = acc[mt][2 * p][2];
                v1.y = acc[mt][2 * p][3];
                v1.z = acc[mt][2 * p + 1][2];
                v1.w = acc[mt][2 * p + 1][3];
                __stcs(reinterpret_cast<float4*>(orow + p * 16), v0);
                __stcs(reinterpret_cast<float4*>(orow + (size_t)8 * VOCAB + p * 16), v1);
            }
        }
    }
}

// ---------------- launch ----------------
extern "C" void kernel_launch(void* const* d_in, const int* in_sizes, int n_in,
                              void* d_out, int out_size) {
    const float* emb  = (const float*)d_in[0];   // [32000, 64] f32
    const float* Wm   = (const float*)d_in[1];   // [32000, 64] f32
    const float* bias = (const float*)d_in[2];   // [32000] f32
    const int*   x    = (const int*)d_in[3];     // [4, 2048] i32
    float* out = (float*)d_out;                  // [4, 2048, 32000] f32

    prep_kernel<<<dim3(32, BATCH), 512>>>(emb, x);

    dim3 grid(VOCAB / BN, 8);   // (250, 8)
    gemm_kernel<<<grid, 256>>>(Wm, bias, out);
}